// round 5
// baseline (speedup 1.0000x reference)
#include <cuda_runtime.h>
#include <cuda_bf16.h>
#include <mma.h>
#include <math.h>
#include <stdint.h>

using namespace nvcuda;

#define NN 4096
#define ND 256
#define HID 64
#define NH 4
#define NC 16

// ---------------- scratch (static device globals) ---------------------------
__device__ float  g_H1[NN*ND];            // layer-1 features (4 MB)
__device__ float  g_F1[NH*NN];
__device__ float  g_F2[NH*NN];
__device__ float  g_f2max1[NH];
__device__ float4 g_bdf1[NH*NN];          // (f2, B=e^{f2-max}, D=e^{0.01(f2-max)}, 0)
__device__ uint8_t g_adj8[(size_t)NN*NN]; // adjacency as bytes (16.7 MB)
__device__ uint4  g_T[NH*2048];           // per j-pair packed {T1hi,T1lo,T2hi,T2lo}
__device__ __nv_bfloat16 g_Vb[NH*2*NN*80];// per head: [hi|lo][j][80] (col64 = ones)
__device__ float  g_H2[NN*ND];            // ELU(attn1) (4 MB)
__device__ float  g_G2[NN*NC];
__device__ float  g_f1b[NN];
__device__ float  g_f2b[NN];
__device__ float  g_f2max2[1];
__device__ float4 g_bdf2[NN];

// ---------------- packed f32x2 helpers (for attn2) ---------------------------
__device__ __forceinline__ unsigned long long pk2(float a, float b){
    unsigned long long r;
    asm("mov.b64 %0, {%1, %2};" : "=l"(r) : "f"(a), "f"(b));
    return r;
}
__device__ __forceinline__ void upk2(unsigned long long v, float& a, float& b){
    asm("mov.b64 {%0, %1}, %2;" : "=f"(a), "=f"(b) : "l"(v));
}
__device__ __forceinline__ void ffma2(unsigned long long& acc,
                                      unsigned long long x, unsigned long long w){
    asm("fma.rn.f32x2 %0, %1, %2, %0;" : "+l"(acc) : "l"(x), "l"(w));
}

// ---------------- K1: H1 = x @ W1_flat^T -------------------------------------
__global__ void gemm1_kernel(const float* __restrict__ X, const float* __restrict__ W){
    __shared__ float sx[64][17];
    __shared__ float sw[64][17];
    int tid = threadIdx.x;
    int tx = tid & 15, ty = tid >> 4;
    int mb = blockIdx.x * 64, nb = blockIdx.y * 64;
    float acc[4][4] = {};
    for (int kb = 0; kb < ND; kb += 16){
        for (int u = tid; u < 64*16; u += 256){
            int m = u >> 4, k = u & 15;
            sx[m][k] = X[(mb + m)*ND + kb + k];
        }
        for (int u = tid; u < 64*16; u += 256){
            int n = u >> 4, k = u & 15;
            sw[n][k] = W[(nb + n)*ND + kb + k];
        }
        __syncthreads();
#pragma unroll
        for (int k = 0; k < 16; k++){
            float a[4], b[4];
#pragma unroll
            for (int r = 0; r < 4; r++){ a[r] = sx[ty*4 + r][k]; b[r] = sw[tx*4 + r][k]; }
#pragma unroll
            for (int i = 0; i < 4; i++)
#pragma unroll
                for (int j = 0; j < 4; j++) acc[i][j] += a[i]*b[j];
        }
        __syncthreads();
    }
#pragma unroll
    for (int i = 0; i < 4; i++)
#pragma unroll
        for (int j = 0; j < 4; j++)
            g_H1[(mb + ty*4 + i)*ND + nb + tx*4 + j] = acc[i][j];
}

// ---------------- K2: f1/f2 per head -----------------------------------------
__global__ void fvec1_kernel(const float* __restrict__ a1, const float* __restrict__ a2){
    __shared__ float s1[NH][HID], s2[NH][HID];
    int tid = threadIdx.x;
    s1[tid >> 6][tid & 63] = a1[tid];
    s2[tid >> 6][tid & 63] = a2[tid];
    __syncthreads();
    int idx = blockIdx.x*256 + tid;
    int h = idx >> 12, i = idx & (NN-1);
    const float* hr = g_H1 + i*ND + h*HID;
    float f1 = 0.f, f2 = 0.f;
#pragma unroll 8
    for (int d = 0; d < HID; d++){
        float v = hr[d];
        f1 += v * s1[h][d];
        f2 += v * s2[h][d];
    }
    g_F1[idx] = f1; g_F2[idx] = f2;
}

// ---------------- K3: per-head max of f2 -------------------------------------
__global__ void max1_kernel(){
    __shared__ float sm[256];
    int t = threadIdx.x; int h = t >> 6, l = t & 63;
    float m = -INFINITY;
    for (int j = l; j < NN; j += 64) m = fmaxf(m, g_F2[h*NN + j]);
    sm[t] = m; __syncthreads();
    if (l == 0){
        float mm = -INFINITY;
        for (int k = 0; k < 64; k++) mm = fmaxf(mm, sm[h*64 + k]);
        g_f2max1[h] = mm;
    }
}

// ---------------- K4: (f2, B, D) table per head -------------------------------
__global__ void bdf1_kernel(){
    int idx = blockIdx.x*256 + threadIdx.x;
    int h = idx >> 12;
    float f2 = g_F2[idx];
    float d  = f2 - g_f2max1[h];
    g_bdf1[idx] = make_float4(f2, expf(d), expf(0.01f*d), 0.f);
}

// ---------------- K4b: adjacency -> bytes -------------------------------------
__global__ void adj8_kernel(const int* __restrict__ adj){
    size_t idx = (size_t)blockIdx.x*256 + threadIdx.x;   // grid 4096: idx < 1M, 16B each
    const int4* s = reinterpret_cast<const int4*>(adj) + idx*4;
    uint32_t w[4];
#pragma unroll
    for (int q = 0; q < 4; q++){
        int4 v = s[q];
        w[q] = (v.x != 0 ? 1u : 0u) | (v.y != 0 ? 1u : 0u) << 8
             | (v.z != 0 ? 1u : 0u) << 16 | (v.w != 0 ? 1u : 0u) << 24;
    }
    reinterpret_cast<uint4*>(g_adj8)[idx] = make_uint4(w[0], w[1], w[2], w[3]);
}

// ---------------- K4c: packed bf16 hi/lo tables of B, D -----------------------
__global__ void tbl1_kernel(){
    int idx = blockIdx.x*256 + threadIdx.x;   // grid 32 -> 8192 = NH*2048
    int h = idx >> 11, jp = idx & 2047;
    float4 b0 = g_bdf1[h*NN + jp*2], b1 = g_bdf1[h*NN + jp*2 + 1];
    __nv_bfloat16 B0h = __float2bfloat16(b0.y), B1h = __float2bfloat16(b1.y);
    __nv_bfloat16 D0h = __float2bfloat16(b0.z), D1h = __float2bfloat16(b1.z);
    __nv_bfloat16 B0l = __float2bfloat16(b0.y - __bfloat162float(B0h));
    __nv_bfloat16 B1l = __float2bfloat16(b1.y - __bfloat162float(B1h));
    __nv_bfloat16 D0l = __float2bfloat16(b0.z - __bfloat162float(D0h));
    __nv_bfloat16 D1l = __float2bfloat16(b1.z - __bfloat162float(D1h));
    uint4 T;
    T.x = (uint32_t)__bfloat16_as_ushort(B0h) | ((uint32_t)__bfloat16_as_ushort(B1h) << 16);
    T.y = (uint32_t)__bfloat16_as_ushort(B0l) | ((uint32_t)__bfloat16_as_ushort(B1l) << 16);
    T.z = (uint32_t)__bfloat16_as_ushort(D0h) | ((uint32_t)__bfloat16_as_ushort(D1h) << 16);
    T.w = (uint32_t)__bfloat16_as_ushort(D0l) | ((uint32_t)__bfloat16_as_ushort(D1l) << 16);
    g_T[idx] = T;
}

// ---------------- K4d: V bf16 hi/lo with ones column --------------------------
__global__ void vbf_kernel(){
    int tid = threadIdx.x;            // grid (64, NH), 256 threads
    int j = blockIdx.x*64 + (tid >> 2);
    int h = blockIdx.y;
    int fg = tid & 3;
    const float* src = g_H1 + (size_t)j*ND + h*HID + fg*16;
    __nv_bfloat16* dhi = g_Vb + (((size_t)(h*2 + 0))*NN + j)*80 + fg*16;
    __nv_bfloat16* dlo = g_Vb + (((size_t)(h*2 + 1))*NN + j)*80 + fg*16;
#pragma unroll
    for (int f = 0; f < 16; f++){
        float v = src[f];
        __nv_bfloat16 hi = __float2bfloat16(v);
        __nv_bfloat16 lo = __float2bfloat16(v - __bfloat162float(hi));
        dhi[f] = hi; dlo[f] = lo;
    }
    if (fg == 3){
        // cols 64..79: ones column at 64, zeros elsewhere
        __nv_bfloat16 one = __float2bfloat16(1.0f);
        __nv_bfloat16 zero = __float2bfloat16(0.0f);
#pragma unroll
        for (int c = 0; c < 16; c++){
            dhi[16 + c] = (c == 0) ? one : zero;
            dlo[16 + c] = zero;
        }
    }
}

// ---------------- K5: attn1 via wmma bf16 -------------------------------------
// grid (64 rowblocks of 64, NH heads), 128 threads (4 warps = 4 M-slices of 16).
// K-tile 32 j. A mats: P1hi/P1lo/P2hi/P2lo [64][32] bf16 in SMEM.
// B mats: g_Vb global [j][80], N=80 (col 64 = ones -> Z).
__global__ void __launch_bounds__(128) attn1_wmma_kernel(){
    __shared__ __align__(16) unsigned char smem[20992];
    __nv_bfloat16* sP1h = (__nv_bfloat16*)(smem);
    __nv_bfloat16* sP1l = (__nv_bfloat16*)(smem + 4096);
    __nv_bfloat16* sP2h = (__nv_bfloat16*)(smem + 8192);
    __nv_bfloat16* sP2l = (__nv_bfloat16*)(smem + 12288);
    uint4* sT  = (uint4*)(smem + 16384);   // 16 entries
    float* sf2 = (float*)(smem + 16640);   // 32 floats
    float* sepi = (float*)smem;            // epilogue reuse [64][80] f32

    int tid = threadIdx.x;
    int wid = tid >> 5;
    int row0 = blockIdx.x * 64;
    int h = blockIdx.y;
    int r = tid >> 1, jg = tid & 1;        // phase-A: row, j-half(16)

    float f1 = g_F1[h*NN + row0 + r];
    const uint8_t* adjrow = g_adj8 + (size_t)(row0 + r)*NN;

    wmma::fragment<wmma::accumulator,16,16,16,float> G1[5], G2[5];
#pragma unroll
    for (int nt = 0; nt < 5; nt++){
        wmma::fill_fragment(G1[nt], 0.f);
        wmma::fill_fragment(G2[nt], 0.f);
    }
    const __nv_bfloat16* Vhi = g_Vb + ((size_t)(h*2 + 0))*NN*80;
    const __nv_bfloat16* Vlo = g_Vb + ((size_t)(h*2 + 1))*NN*80;

    for (int t = 0; t < 128; t++){
        int j0 = t * 32;
        __syncthreads();   // prev MMA consumed SMEM
        if (tid < 16) sT[tid] = g_T[h*2048 + (j0 >> 1) + tid];
        if (tid < 32) sf2[tid] = g_bdf1[h*NN + j0 + tid].x;
        __syncthreads();
        // ---- phase A: build A-matrices ----
        uint4 av = *reinterpret_cast<const uint4*>(adjrow + j0 + jg*16);
        uint32_t aw[4] = {av.x, av.y, av.z, av.w};
        uint32_t o1h[8], o1l[8], o2h[8], o2l[8];
#pragma unroll
        for (int p = 0; p < 8; p++){
            int jj = jg*16 + p*2;
            float s0 = f1 + sf2[jj];
            float s1 = f1 + sf2[jj + 1];
            uint32_t word = aw[p >> 1];
            uint32_t sh = (p & 1) * 16;
            bool a0 = ((word >> sh) & 0xFF) != 0;
            bool a1 = ((word >> (sh + 8)) & 0xFF) != 0;
            uint4 T = sT[jg*8 + p];
            uint32_t m = ((a0 && s0 > 0.f) ? 0x0000FFFFu : 0u)
                       | ((a1 && s1 > 0.f) ? 0xFFFF0000u : 0u);
            uint32_t n = ((a0 && s0 < 0.f) ? 0x0000FFFFu : 0u)
                       | ((a1 && s1 < 0.f) ? 0xFFFF0000u : 0u);
            o1h[p] = T.x & m; o1l[p] = T.y & m;
            o2h[p] = T.z & n; o2l[p] = T.w & n;
        }
        {
            int off = r*32 + jg*16;   // elements
            uint4* d1h = reinterpret_cast<uint4*>(sP1h + off);
            uint4* d1l = reinterpret_cast<uint4*>(sP1l + off);
            uint4* d2h = reinterpret_cast<uint4*>(sP2h + off);
            uint4* d2l = reinterpret_cast<uint4*>(sP2l + off);
            d1h[0] = make_uint4(o1h[0],o1h[1],o1h[2],o1h[3]);
            d1h[1] = make_uint4(o1h[4],o1h[5],o1h[6],o1h[7]);
            d1l[0] = make_uint4(o1l[0],o1l[1],o1l[2],o1l[3]);
            d1l[1] = make_uint4(o1l[4],o1l[5],o1l[6],o1l[7]);
            d2h[0] = make_uint4(o2h[0],o2h[1],o2h[2],o2h[3]);
            d2h[1] = make_uint4(o2h[4],o2h[5],o2h[6],o2h[7]);
            d2l[0] = make_uint4(o2l[0],o2l[1],o2l[2],o2l[3]);
            d2l[1] = make_uint4(o2l[4],o2l[5],o2l[6],o2l[7]);
        }
        __syncthreads();
        // ---- phase B: wmma, warp wid handles rows wid*16..+15 ----
        const __nv_bfloat16* A1h = sP1h + wid*16*32;
        const __nv_bfloat16* A1l = sP1l + wid*16*32;
        const __nv_bfloat16* A2h = sP2h + wid*16*32;
        const __nv_bfloat16* A2l = sP2l + wid*16*32;
#pragma unroll
        for (int ks = 0; ks < 2; ks++){
            wmma::fragment<wmma::matrix_a,16,16,16,__nv_bfloat16,wmma::row_major> a1h, a1l, a2h, a2l;
            wmma::load_matrix_sync(a1h, A1h + ks*16, 32);
            wmma::load_matrix_sync(a1l, A1l + ks*16, 32);
            wmma::load_matrix_sync(a2h, A2h + ks*16, 32);
            wmma::load_matrix_sync(a2l, A2l + ks*16, 32);
            const __nv_bfloat16* bh0 = Vhi + (size_t)(j0 + ks*16)*80;
            const __nv_bfloat16* bl0 = Vlo + (size_t)(j0 + ks*16)*80;
#pragma unroll
            for (int nt = 0; nt < 5; nt++){
                wmma::fragment<wmma::matrix_b,16,16,16,__nv_bfloat16,wmma::row_major> bh, bl;
                wmma::load_matrix_sync(bh, bh0 + nt*16, 80);
                wmma::load_matrix_sync(bl, bl0 + nt*16, 80);
                wmma::mma_sync(G1[nt], a1h, bh, G1[nt]);
                wmma::mma_sync(G1[nt], a1l, bh, G1[nt]);
                wmma::mma_sync(G1[nt], a1h, bl, G1[nt]);
                wmma::mma_sync(G2[nt], a2h, bh, G2[nt]);
                wmma::mma_sync(G2[nt], a2l, bh, G2[nt]);
                wmma::mma_sync(G2[nt], a2h, bl, G2[nt]);
            }
        }
    }
    // ---- epilogue ----
    float tt = f1 + g_f2max1[h];
    float M  = tt > 0.f ? tt : 0.01f*tt;
    float alpha = expf(tt - M), beta = expf(0.01f*tt - M);
    int half = tid & 1;

    __syncthreads();
#pragma unroll
    for (int nt = 0; nt < 5; nt++)
        wmma::store_matrix_sync(sepi + wid*16*80 + nt*16, G1[nt], 80, wmma::mem_row_major);
    __syncthreads();
    float buf[32];
#pragma unroll
    for (int c = 0; c < 32; c++) buf[c] = alpha * sepi[r*80 + half*32 + c];
    float z1 = alpha * sepi[r*80 + 64];
    __syncthreads();
#pragma unroll
    for (int nt = 0; nt < 5; nt++)
        wmma::store_matrix_sync(sepi + wid*16*80 + nt*16, G2[nt], 80, wmma::mem_row_major);
    __syncthreads();
    float Z = z1 + beta * sepi[r*80 + 64];
    float rz = 1.f / Z;
    float* dst = g_H2 + (size_t)(row0 + r)*ND + h*HID + half*32;
#pragma unroll
    for (int c = 0; c < 32; c += 4){
        float o[4];
#pragma unroll
        for (int e = 0; e < 4; e++){
            float v = (buf[c+e] + beta * sepi[r*80 + half*32 + c + e]) * rz;
            o[e] = v > 0.f ? v : expm1f(v);
        }
        *reinterpret_cast<float4*>(dst + c) = make_float4(o[0], o[1], o[2], o[3]);
    }
}

// ---------------- K6: G2 = H2 @ W2^T + layer-2 f-vectors ----------------------
__global__ void gemm2_kernel(const float* __restrict__ W2,
                             const float* __restrict__ a1, const float* __restrict__ a2){
    __shared__ float sW[16][257];
    __shared__ float sa1[16], sa2[16];
    int tid = threadIdx.x;
    for (int u = tid; u < 16*256; u += 256) sW[u >> 8][u & 255] = W2[u];
    if (tid < 16){ sa1[tid] = a1[tid]; sa2[tid] = a2[tid]; }
    __syncthreads();
    int idx = blockIdx.x*256 + tid;
    int i = idx >> 4, c = idx & 15;
    const float4* hr = reinterpret_cast<const float4*>(g_H2 + i*ND);
    float acc = 0.f;
#pragma unroll 4
    for (int k4 = 0; k4 < 64; k4++){
        float4 v = hr[k4];
        acc += v.x*sW[c][k4*4] + v.y*sW[c][k4*4+1] + v.z*sW[c][k4*4+2] + v.w*sW[c][k4*4+3];
    }
    g_G2[idx] = acc;
    float u1 = acc*sa1[c], u2 = acc*sa2[c];
#pragma unroll
    for (int off = 8; off > 0; off >>= 1){
        u1 += __shfl_down_sync(0xffffffffu, u1, off, 16);
        u2 += __shfl_down_sync(0xffffffffu, u2, off, 16);
    }
    if (c == 0){ g_f1b[i] = u1; g_f2b[i] = u2; }
}

// ---------------- K7/K8: layer-2 max + table ----------------------------------
__global__ void max2_kernel(){
    __shared__ float sm[256];
    int t = threadIdx.x; float m = -INFINITY;
    for (int j = t; j < NN; j += 256) m = fmaxf(m, g_f2b[j]);
    sm[t] = m; __syncthreads();
    for (int off = 128; off > 0; off >>= 1){
        if (t < off) sm[t] = fmaxf(sm[t], sm[t + off]);
        __syncthreads();
    }
    if (t == 0) g_f2max2[0] = sm[0];
}
__global__ void bdf2_kernel(){
    int j = blockIdx.x*256 + threadIdx.x;
    float f2 = g_f2b[j];
    float d  = f2 - g_f2max2[0];
    g_bdf2[j] = make_float4(f2, expf(d), expf(0.01f*d), 0.f);
}

// ---------------- K9: layer-2 attention -> logits -----------------------------
__global__ void attn2_kernel(const int* __restrict__ adj, float* __restrict__ out){
    __shared__ int    s_adj[32][129];
    __shared__ float4 s_bdf[128];
    __shared__ float  sred[32][8][17];
    int tid  = threadIdx.x;
    int rloc = tid >> 3;
    int jl   = tid & 7;
    int row  = blockIdx.x * 32 + rloc;

    float f1 = g_f1b[row];
    float t  = f1 + g_f2max2[0];
    float M  = t > 0.f ? t : 0.01f*t;
    float A  = expf(t - M), C = expf(0.01f*t - M);
    unsigned long long acc[8];
#pragma unroll
    for (int q = 0; q < 8; q++) acc[q] = 0ull;
    float Z = 0.f;

    const int* arow = adj + blockIdx.x * 32 * NN;
    for (int j0 = 0; j0 < NN; j0 += 128){
        if (j0) __syncthreads();
        for (int u = tid; u < 32*128; u += 256){
            int rr = u >> 7, cc = u & 127;
            s_adj[rr][cc] = arow[rr*NN + j0 + cc];
        }
        if (tid < 128) s_bdf[tid] = g_bdf2[j0 + tid];
        __syncthreads();
        for (int jj = jl; jj < 128; jj += 8){
            int a = s_adj[rloc][jj];
            float4 bdf = s_bdf[jj];
            float s = f1 + bdf.x;
            float w = (s > 0.f) ? (A*bdf.y) : (C*bdf.z);
            if ((a == 0) | (s == 0.f)) w = 0.f;
            Z += w;
            const ulonglong2* p = reinterpret_cast<const ulonglong2*>(g_G2 + (j0 + jj)*NC);
            ulonglong2 q0 = p[0], q1 = p[1], q2 = p[2], q3 = p[3];
            unsigned long long wp = pk2(w, w);
            ffma2(acc[0], q0.x, wp); ffma2(acc[1], q0.y, wp);
            ffma2(acc[2], q1.x, wp); ffma2(acc[3], q1.y, wp);
            ffma2(acc[4], q2.x, wp); ffma2(acc[5], q2.y, wp);
            ffma2(acc[6], q3.x, wp); ffma2(acc[7], q3.y, wp);
        }
    }
#pragma unroll
    for (int q = 0; q < 8; q++){
        float x0, x1; upk2(acc[q], x0, x1);
        sred[rloc][jl][2*q]   = x0;
        sred[rloc][jl][2*q+1] = x1;
    }
    sred[rloc][jl][16] = Z;
    __syncthreads();
    for (int u = tid; u < 32*16; u += 256){
        int r = u >> 4, f = u & 15;
        float sum = 0.f, zz = 0.f;
#pragma unroll
        for (int l = 0; l < 8; l++){ sum += sred[r][l][f]; zz += sred[r][l][16]; }
        out[(blockIdx.x*32 + r)*NC + f] = sum / zz;
    }
}

// ---------------- launch ------------------------------------------------------
extern "C" void kernel_launch(void* const* d_in, const int* in_sizes, int n_in,
                              void* d_out, int out_size){
    const float* x    = (const float*)d_in[0];
    const int*   adj  = (const int*)  d_in[1];
    const float* W1   = (const float*)d_in[2];
    const float* a1_1 = (const float*)d_in[3];
    const float* a2_1 = (const float*)d_in[4];
    const float* W2   = (const float*)d_in[5];
    const float* a1_2 = (const float*)d_in[6];
    const float* a2_2 = (const float*)d_in[7];
    float* out = (float*)d_out;

    adj8_kernel<<<4096, 256>>>(adj);
    gemm1_kernel<<<dim3(64, 4), 256>>>(x, W1);
    fvec1_kernel<<<64, 256>>>(a1_1, a2_1);
    max1_kernel<<<1, 256>>>();
    bdf1_kernel<<<64, 256>>>();
    tbl1_kernel<<<32, 256>>>();
    vbf_kernel<<<dim3(64, NH), 256>>>();
    attn1_wmma_kernel<<<dim3(64, NH), 128>>>();
    gemm2_kernel<<<256, 256>>>(W2, a1_2, a2_2);
    max2_kernel<<<1, 256>>>();
    bdf2_kernel<<<16, 256>>>();
    attn2_kernel<<<128, 256>>>(adj, out);
}

// round 6
// speedup vs baseline: 1.5031x; 1.5031x over previous
#include <cuda_runtime.h>
#include <cuda_fp16.h>
#include <mma.h>
#include <math.h>
#include <stdint.h>

using namespace nvcuda;

#define NN 4096
#define ND 256
#define HID 64
#define NH 4
#define NC 16

// ---------------- scratch (static device globals) ---------------------------
__device__ float  g_H1[NN*ND];            // layer-1 features (4 MB)
__device__ float  g_F1[NH*NN];
__device__ float  g_F2[NH*NN];
__device__ float  g_f2max1[NH];
__device__ float4 g_bdf1[NH*NN];          // (f2, B=e^{f2-max}, D=e^{0.01(f2-max)}, 0)
__device__ uint8_t g_adj8[(size_t)NN*NN]; // adjacency as bytes (16.7 MB)
__device__ __half g_Vb[(size_t)NH*2*NN*80]; // per head: [hi|lo][j][80] (col64 = ones)
__device__ float  g_H2[NN*ND];            // ELU(attn1) (4 MB)
__device__ float  g_G2[NN*NC];
__device__ __half g_G2b[2*NN*32];         // [hi|lo][j][32] (col16 = ones)
__device__ float  g_f1b[NN];
__device__ float  g_f2b[NN];
__device__ float  g_f2max2[1];
__device__ float4 g_bdf2[NN];

// ---------------- K1: H1 = x @ W1_flat^T -------------------------------------
__global__ void gemm1_kernel(const float* __restrict__ X, const float* __restrict__ W){
    __shared__ float sx[64][17];
    __shared__ float sw[64][17];
    int tid = threadIdx.x;
    int tx = tid & 15, ty = tid >> 4;
    int mb = blockIdx.x * 64, nb = blockIdx.y * 64;
    float acc[4][4] = {};
    for (int kb = 0; kb < ND; kb += 16){
        for (int u = tid; u < 64*16; u += 256){
            int m = u >> 4, k = u & 15;
            sx[m][k] = X[(mb + m)*ND + kb + k];
        }
        for (int u = tid; u < 64*16; u += 256){
            int n = u >> 4, k = u & 15;
            sw[n][k] = W[(nb + n)*ND + kb + k];
        }
        __syncthreads();
#pragma unroll
        for (int k = 0; k < 16; k++){
            float a[4], b[4];
#pragma unroll
            for (int r = 0; r < 4; r++){ a[r] = sx[ty*4 + r][k]; b[r] = sw[tx*4 + r][k]; }
#pragma unroll
            for (int i = 0; i < 4; i++)
#pragma unroll
                for (int j = 0; j < 4; j++) acc[i][j] += a[i]*b[j];
        }
        __syncthreads();
    }
#pragma unroll
    for (int i = 0; i < 4; i++)
#pragma unroll
        for (int j = 0; j < 4; j++)
            g_H1[(mb + ty*4 + i)*ND + nb + tx*4 + j] = acc[i][j];
}

// ---------------- K2: f1/f2 per head -----------------------------------------
__global__ void fvec1_kernel(const float* __restrict__ a1, const float* __restrict__ a2){
    __shared__ float s1[NH][HID], s2[NH][HID];
    int tid = threadIdx.x;
    s1[tid >> 6][tid & 63] = a1[tid];
    s2[tid >> 6][tid & 63] = a2[tid];
    __syncthreads();
    int idx = blockIdx.x*256 + tid;
    int h = idx >> 12, i = idx & (NN-1);
    const float* hr = g_H1 + i*ND + h*HID;
    float f1 = 0.f, f2 = 0.f;
#pragma unroll 8
    for (int d = 0; d < HID; d++){
        float v = hr[d];
        f1 += v * s1[h][d];
        f2 += v * s2[h][d];
    }
    g_F1[idx] = f1; g_F2[idx] = f2;
}

// ---------------- K3: per-head max of f2 (one block per head) -----------------
__global__ void max1_kernel(){
    int h = blockIdx.x, t = threadIdx.x;
    __shared__ float sm[8];
    float m = -INFINITY;
    for (int j = t; j < NN; j += 256) m = fmaxf(m, g_F2[h*NN + j]);
#pragma unroll
    for (int off = 16; off > 0; off >>= 1) m = fmaxf(m, __shfl_down_sync(0xffffffffu, m, off));
    if ((t & 31) == 0) sm[t >> 5] = m;
    __syncthreads();
    if (t == 0){
        float mm = sm[0];
#pragma unroll
        for (int k = 1; k < 8; k++) mm = fmaxf(mm, sm[k]);
        g_f2max1[h] = mm;
    }
}

// ---------------- K4: (f2, B, D) table per head -------------------------------
__global__ void bdf1_kernel(){
    int idx = blockIdx.x*256 + threadIdx.x;
    int h = idx >> 12;
    float f2 = g_F2[idx];
    float d  = f2 - g_f2max1[h];
    g_bdf1[idx] = make_float4(f2, expf(d), expf(0.01f*d), 0.f);
}

// ---------------- K4b: adjacency -> bytes -------------------------------------
__global__ void adj8_kernel(const int* __restrict__ adj){
    size_t idx = (size_t)blockIdx.x*256 + threadIdx.x;   // grid 4096
    const int4* s = reinterpret_cast<const int4*>(adj) + idx*4;
    uint32_t w[4];
#pragma unroll
    for (int q = 0; q < 4; q++){
        int4 v = s[q];
        w[q] = (v.x != 0 ? 1u : 0u) | (v.y != 0 ? 1u : 0u) << 8
             | (v.z != 0 ? 1u : 0u) << 16 | (v.w != 0 ? 1u : 0u) << 24;
    }
    reinterpret_cast<uint4*>(g_adj8)[idx] = make_uint4(w[0], w[1], w[2], w[3]);
}

// ---------------- helper: pack two halves -------------------------------------
__device__ __forceinline__ uint32_t packh(__half a, __half b){
    return (uint32_t)__half_as_ushort(a) | ((uint32_t)__half_as_ushort(b) << 16);
}

// ---------------- K4c: V fp16 hi/lo with ones column --------------------------
__global__ void vbf_kernel(){
    int tid = threadIdx.x;            // grid (64, NH), 256 threads
    int j = blockIdx.x*64 + (tid >> 2);
    int h = blockIdx.y;
    int fg = tid & 3;
    const float4* src = reinterpret_cast<const float4*>(g_H1 + (size_t)j*ND + h*HID + fg*16);
    __half* dhi = g_Vb + (((size_t)(h*2 + 0))*NN + j)*80 + fg*16;
    __half* dlo = g_Vb + (((size_t)(h*2 + 1))*NN + j)*80 + fg*16;
    uint32_t ph[8], pl[8];
#pragma unroll
    for (int q = 0; q < 4; q++){
        float4 v = src[q];
        float e[4] = {v.x, v.y, v.z, v.w};
        __half hh[4], ll[4];
#pragma unroll
        for (int k = 0; k < 4; k++){
            hh[k] = __float2half_rn(e[k]);
            ll[k] = __float2half_rn(e[k] - __half2float(hh[k]));
        }
        ph[q*2]   = packh(hh[0], hh[1]); ph[q*2+1] = packh(hh[2], hh[3]);
        pl[q*2]   = packh(ll[0], ll[1]); pl[q*2+1] = packh(ll[2], ll[3]);
    }
    uint4* oh = reinterpret_cast<uint4*>(dhi);
    uint4* ol = reinterpret_cast<uint4*>(dlo);
    oh[0] = make_uint4(ph[0],ph[1],ph[2],ph[3]);
    oh[1] = make_uint4(ph[4],ph[5],ph[6],ph[7]);
    ol[0] = make_uint4(pl[0],pl[1],pl[2],pl[3]);
    ol[1] = make_uint4(pl[4],pl[5],pl[6],pl[7]);
    if (fg == 3){   // cols 64..79: ones at 64, zeros elsewhere
        uint4* zh = reinterpret_cast<uint4*>(dhi + 16);
        uint4* zl = reinterpret_cast<uint4*>(dlo + 16);
        zh[0] = make_uint4(0x00003C00u, 0u, 0u, 0u);   // half(1.0)=0x3C00
        zh[1] = make_uint4(0u, 0u, 0u, 0u);
        zl[0] = make_uint4(0u, 0u, 0u, 0u);
        zl[1] = make_uint4(0u, 0u, 0u, 0u);
    }
}

// ---------------- K5: attn1 via wmma fp16, SMEM-staged B ----------------------
// grid (64 rowblocks, NH), 128 threads (4 warps x 16 rows). K-tile 64 j. N=80.
__global__ void __launch_bounds__(128) attn1_wmma_kernel(){
    __shared__ __align__(16) unsigned char smem[36864];
    __half* sAh = (__half*)(smem);             // [64][64] 8KB
    __half* sAl = (__half*)(smem + 8192);      // 8KB
    __half* sBh = (__half*)(smem + 16384);     // [64][80] 10KB
    __half* sBl = (__half*)(smem + 26624);     // 10KB
    float*  sepi = (float*)smem;               // epilogue [64][80] 20KB (reuse)
    __shared__ float sf2[64], sBv[64], sDv[64];

    int tid = threadIdx.x;
    int wid = tid >> 5;
    int row0 = blockIdx.x * 64;
    int h = blockIdx.y;
    int r = tid >> 1, jg = tid & 1;

    float f1 = g_F1[h*NN + row0 + r];
    float tt = f1 + g_f2max1[h];
    float M  = tt > 0.f ? tt : 0.01f*tt;
    float alpha = expf(tt - M), beta = expf(0.01f*tt - M);

    wmma::fragment<wmma::accumulator,16,16,16,float> G[5];
#pragma unroll
    for (int nt = 0; nt < 5; nt++) wmma::fill_fragment(G[nt], 0.f);

    const __half* Vh = g_Vb + ((size_t)(h*2 + 0))*NN*80;
    const __half* Vl = g_Vb + ((size_t)(h*2 + 1))*NN*80;
    const uint8_t* adjrow = g_adj8 + (size_t)(row0 + r)*NN;

    for (int t = 0; t < 64; t++){
        int j0 = t * 64;
        __syncthreads();
        if (tid < 64){
            float4 b = g_bdf1[h*NN + j0 + tid];
            sf2[tid] = b.x; sBv[tid] = b.y; sDv[tid] = b.z;
        }
        {   // stage B tile: 64 rows x 80 halves, hi+lo
            int j = tid >> 1, ch = (tid & 1)*40;
            const uint4* srch = reinterpret_cast<const uint4*>(Vh + (size_t)(j0 + j)*80 + ch);
            const uint4* srcl = reinterpret_cast<const uint4*>(Vl + (size_t)(j0 + j)*80 + ch);
            uint4* dsth = reinterpret_cast<uint4*>(sBh + j*80 + ch);
            uint4* dstl = reinterpret_cast<uint4*>(sBl + j*80 + ch);
#pragma unroll
            for (int q = 0; q < 5; q++){ dsth[q] = srch[q]; dstl[q] = srcl[q]; }
        }
        __syncthreads();
        // ---- phase A: build fused-weight A-matrix (hi/lo) ----
        uint4 a0 = *reinterpret_cast<const uint4*>(adjrow + j0 + jg*32);
        uint4 a1 = *reinterpret_cast<const uint4*>(adjrow + j0 + jg*32 + 16);
        uint32_t aw[8] = {a0.x, a0.y, a0.z, a0.w, a1.x, a1.y, a1.z, a1.w};
        uint32_t oh[16], ol[16];
#pragma unroll
        for (int p = 0; p < 16; p++){
            uint32_t hw[2], lw[2];
#pragma unroll
            for (int e = 0; e < 2; e++){
                int jl = 2*p + e;
                int jj = jg*32 + jl;
                uint32_t byte = (aw[jl >> 2] >> ((jl & 3)*8)) & 0xFFu;
                float s = f1 + sf2[jj];
                float w = s > 0.f ? alpha*sBv[jj] : beta*sDv[jj];
                if ((byte == 0u) | (s == 0.f)) w = 0.f;
                __half whf = __float2half_rn(w);
                __half wlf = __float2half_rn(w - __half2float(whf));
                hw[e] = __half_as_ushort(whf);
                lw[e] = __half_as_ushort(wlf);
            }
            oh[p] = hw[0] | (hw[1] << 16);
            ol[p] = lw[0] | (lw[1] << 16);
        }
        {
            uint4* dh = reinterpret_cast<uint4*>(sAh + r*64 + jg*32);
            uint4* dl = reinterpret_cast<uint4*>(sAl + r*64 + jg*32);
#pragma unroll
            for (int k = 0; k < 4; k++){
                dh[k] = make_uint4(oh[4*k], oh[4*k+1], oh[4*k+2], oh[4*k+3]);
                dl[k] = make_uint4(ol[4*k], ol[4*k+1], ol[4*k+2], ol[4*k+3]);
            }
        }
        __syncthreads();
        // ---- phase B ----
#pragma unroll
        for (int ks = 0; ks < 4; ks++){
            wmma::fragment<wmma::matrix_a,16,16,16,__half,wmma::row_major> ah, al;
            wmma::load_matrix_sync(ah, sAh + wid*16*64 + ks*16, 64);
            wmma::load_matrix_sync(al, sAl + wid*16*64 + ks*16, 64);
#pragma unroll
            for (int nt = 0; nt < 5; nt++){
                wmma::fragment<wmma::matrix_b,16,16,16,__half,wmma::row_major> bh, bl;
                wmma::load_matrix_sync(bh, sBh + ks*16*80 + nt*16, 80);
                wmma::load_matrix_sync(bl, sBl + ks*16*80 + nt*16, 80);
                wmma::mma_sync(G[nt], ah, bh, G[nt]);
                wmma::mma_sync(G[nt], al, bh, G[nt]);
                wmma::mma_sync(G[nt], ah, bl, G[nt]);
            }
        }
    }
    // ---- epilogue ----
    __syncthreads();
#pragma unroll
    for (int nt = 0; nt < 5; nt++)
        wmma::store_matrix_sync(sepi + wid*16*80 + nt*16, G[nt], 80, wmma::mem_row_major);
    __syncthreads();
    float rz = 1.f / sepi[r*80 + 64];
    float* dst = g_H2 + (size_t)(row0 + r)*ND + h*HID + jg*32;
#pragma unroll
    for (int c = 0; c < 32; c += 4){
        float o[4];
#pragma unroll
        for (int e = 0; e < 4; e++){
            float v = sepi[r*80 + jg*32 + c + e] * rz;
            o[e] = v > 0.f ? v : expm1f(v);
        }
        *reinterpret_cast<float4*>(dst + c) = make_float4(o[0], o[1], o[2], o[3]);
    }
}

// ---------------- K6: G2 = H2 @ W2^T + layer-2 f-vectors ----------------------
__global__ void gemm2_kernel(const float* __restrict__ W2,
                             const float* __restrict__ a1, const float* __restrict__ a2){
    __shared__ float sW[16][257];
    __shared__ float sa1[16], sa2[16];
    int tid = threadIdx.x;
    for (int u = tid; u < 16*256; u += 256) sW[u >> 8][u & 255] = W2[u];
    if (tid < 16){ sa1[tid] = a1[tid]; sa2[tid] = a2[tid]; }
    __syncthreads();
    int idx = blockIdx.x*256 + tid;
    int i = idx >> 4, c = idx & 15;
    const float4* hr = reinterpret_cast<const float4*>(g_H2 + i*ND);
    float acc = 0.f;
#pragma unroll 4
    for (int k4 = 0; k4 < 64; k4++){
        float4 v = hr[k4];
        acc += v.x*sW[c][k4*4] + v.y*sW[c][k4*4+1] + v.z*sW[c][k4*4+2] + v.w*sW[c][k4*4+3];
    }
    g_G2[idx] = acc;
    float u1 = acc*sa1[c], u2 = acc*sa2[c];
#pragma unroll
    for (int off = 8; off > 0; off >>= 1){
        u1 += __shfl_down_sync(0xffffffffu, u1, off, 16);
        u2 += __shfl_down_sync(0xffffffffu, u2, off, 16);
    }
    if (c == 0){ g_f1b[i] = u1; g_f2b[i] = u2; }
}

// ---------------- K7/K8: layer-2 max + table ----------------------------------
__global__ void max2_kernel(){
    __shared__ float sm[256];
    int t = threadIdx.x; float m = -INFINITY;
    for (int j = t; j < NN; j += 256) m = fmaxf(m, g_f2b[j]);
    sm[t] = m; __syncthreads();
    for (int off = 128; off > 0; off >>= 1){
        if (t < off) sm[t] = fmaxf(sm[t], sm[t + off]);
        __syncthreads();
    }
    if (t == 0) g_f2max2[0] = sm[0];
}
__global__ void bdf2_kernel(){
    int j = blockIdx.x*256 + threadIdx.x;
    float f2 = g_f2b[j];
    float d  = f2 - g_f2max2[0];
    g_bdf2[j] = make_float4(f2, expf(d), expf(0.01f*d), 0.f);
}

// ---------------- K8b: G2 -> fp16 hi/lo with ones column ----------------------
__global__ void g2split_kernel(){
    int row = blockIdx.x*256 + threadIdx.x;   // grid 16
    const float4* src = reinterpret_cast<const float4*>(g_G2 + row*NC);
    uint32_t ph[16], pl[16];
#pragma unroll
    for (int q = 0; q < 4; q++){
        float4 v = src[q];
        float e[4] = {v.x, v.y, v.z, v.w};
        __half hh[4], ll[4];
#pragma unroll
        for (int k = 0; k < 4; k++){
            hh[k] = __float2half_rn(e[k]);
            ll[k] = __float2half_rn(e[k] - __half2float(hh[k]));
        }
        ph[q*2]   = packh(hh[0], hh[1]); ph[q*2+1] = packh(hh[2], hh[3]);
        pl[q*2]   = packh(ll[0], ll[1]); pl[q*2+1] = packh(ll[2], ll[3]);
    }
    ph[8] = 0x00003C00u; pl[8] = 0u;          // ones col at 16
#pragma unroll
    for (int k = 9; k < 16; k++){ ph[k] = 0u; pl[k] = 0u; }
    uint4* dh = reinterpret_cast<uint4*>(g_G2b + ((size_t)0*NN + row)*32);
    uint4* dl = reinterpret_cast<uint4*>(g_G2b + ((size_t)1*NN + row)*32);
#pragma unroll
    for (int k = 0; k < 4; k++){
        dh[k] = make_uint4(ph[4*k], ph[4*k+1], ph[4*k+2], ph[4*k+3]);
        dl[k] = make_uint4(pl[4*k], pl[4*k+1], pl[4*k+2], pl[4*k+3]);
    }
}

// ---------------- K9: attn2 via wmma fp16 -> logits ---------------------------
// grid 64 rowblocks, 128 threads. K-tile 64, N=32 (16 classes + ones@16).
__global__ void __launch_bounds__(128) attn2_wmma_kernel(float* __restrict__ out){
    __shared__ __align__(16) unsigned char smem[24576];
    __half* sAh = (__half*)(smem);             // [64][64] 8KB
    __half* sAl = (__half*)(smem + 8192);      // 8KB
    __half* sBh = (__half*)(smem + 16384);     // [64][32] 4KB
    __half* sBl = (__half*)(smem + 20480);     // 4KB
    float*  sepi = (float*)smem;               // [64][32] 8KB (reuse)
    __shared__ float sf2[64], sBv[64], sDv[64];

    int tid = threadIdx.x;
    int wid = tid >> 5;
    int row0 = blockIdx.x * 64;
    int r = tid >> 1, jg = tid & 1;

    float f1 = g_f1b[row0 + r];
    float tt = f1 + g_f2max2[0];
    float M  = tt > 0.f ? tt : 0.01f*tt;
    float alpha = expf(tt - M), beta = expf(0.01f*tt - M);

    wmma::fragment<wmma::accumulator,16,16,16,float> G[2];
    wmma::fill_fragment(G[0], 0.f);
    wmma::fill_fragment(G[1], 0.f);

    const uint8_t* adjrow = g_adj8 + (size_t)(row0 + r)*NN;

    for (int t = 0; t < 64; t++){
        int j0 = t * 64;
        __syncthreads();
        if (tid < 64){
            float4 b = g_bdf2[j0 + tid];
            sf2[tid] = b.x; sBv[tid] = b.y; sDv[tid] = b.z;
        }
        {   // stage B: 64 rows x 32 halves = 64B/row, hi+lo
            int j = tid >> 1, part = tid & 1;
            const uint4* src = reinterpret_cast<const uint4*>(
                g_G2b + ((size_t)part*NN + j0 + j)*32);
            uint4* dst = reinterpret_cast<uint4*>((part ? sBl : sBh) + j*32);
#pragma unroll
            for (int q = 0; q < 4; q++) dst[q] = src[q];
        }
        __syncthreads();
        uint4 a0 = *reinterpret_cast<const uint4*>(adjrow + j0 + jg*32);
        uint4 a1 = *reinterpret_cast<const uint4*>(adjrow + j0 + jg*32 + 16);
        uint32_t aw[8] = {a0.x, a0.y, a0.z, a0.w, a1.x, a1.y, a1.z, a1.w};
        uint32_t oh[16], ol[16];
#pragma unroll
        for (int p = 0; p < 16; p++){
            uint32_t hw[2], lw[2];
#pragma unroll
            for (int e = 0; e < 2; e++){
                int jl = 2*p + e;
                int jj = jg*32 + jl;
                uint32_t byte = (aw[jl >> 2] >> ((jl & 3)*8)) & 0xFFu;
                float s = f1 + sf2[jj];
                float w = s > 0.f ? alpha*sBv[jj] : beta*sDv[jj];
                if ((byte == 0u) | (s == 0.f)) w = 0.f;
                __half whf = __float2half_rn(w);
                __half wlf = __float2half_rn(w - __half2float(whf));
                hw[e] = __half_as_ushort(whf);
                lw[e] = __half_as_ushort(wlf);
            }
            oh[p] = hw[0] | (hw[1] << 16);
            ol[p] = lw[0] | (lw[1] << 16);
        }
        {
            uint4* dh = reinterpret_cast<uint4*>(sAh + r*64 + jg*32);
            uint4* dl = reinterpret_cast<uint4*>(sAl + r*64 + jg*32);
#pragma unroll
            for (int k = 0; k < 4; k++){
                dh[k] = make_uint4(oh[4*k], oh[4*k+1], oh[4*k+2], oh[4*k+3]);
                dl[k] = make_uint4(ol[4*k], ol[4*k+1], ol[4*k+2], ol[4*k+3]);
            }
        }
        __syncthreads();
#pragma unroll
        for (int ks = 0; ks < 4; ks++){
            wmma::fragment<wmma::matrix_a,16,16,16,__half,wmma::row_major> ah, al;
            wmma::load_matrix_sync(ah, sAh + wid*16*64 + ks*16, 64);
            wmma::load_matrix_sync(al, sAl + wid*16*64 + ks*16, 64);
#pragma unroll
            for (int nt = 0; nt < 2; nt++){
                wmma::fragment<wmma::matrix_b,16,16,16,__half,wmma::row_major> bh, bl;
                wmma::load_matrix_sync(bh, sBh + ks*16*32 + nt*16, 32);
                wmma::load_matrix_sync(bl, sBl + ks*16*32 + nt*16, 32);
                wmma::mma_sync(G[nt], ah, bh, G[nt]);
                wmma::mma_sync(G[nt], al, bh, G[nt]);
                wmma::mma_sync(G[nt], ah, bl, G[nt]);
            }
        }
    }
    __syncthreads();
    wmma::store_matrix_sync(sepi + wid*16*32,      G[0], 32, wmma::mem_row_major);
    wmma::store_matrix_sync(sepi + wid*16*32 + 16, G[1], 32, wmma::mem_row_major);
    __syncthreads();
    float rz = 1.f / sepi[r*32 + 16];
    float* dst = out + (size_t)(row0 + r)*NC + jg*8;
#pragma unroll
    for (int c = 0; c < 8; c += 4){
        float o[4];
#pragma unroll
        for (int e = 0; e < 4; e++) o[e] = sepi[r*32 + jg*8 + c + e] * rz;
        *reinterpret_cast<float4*>(dst + c) = make_float4(o[0], o[1], o[2], o[3]);
    }
}

// ---------------- launch ------------------------------------------------------
extern "C" void kernel_launch(void* const* d_in, const int* in_sizes, int n_in,
                              void* d_out, int out_size){
    const float* x    = (const float*)d_in[0];
    const int*   adj  = (const int*)  d_in[1];
    const float* W1   = (const float*)d_in[2];
    const float* a1_1 = (const float*)d_in[3];
    const float* a2_1 = (const float*)d_in[4];
    const float* W2   = (const float*)d_in[5];
    const float* a1_2 = (const float*)d_in[6];
    const float* a2_2 = (const float*)d_in[7];
    float* out = (float*)d_out;

    adj8_kernel<<<4096, 256>>>(adj);
    gemm1_kernel<<<dim3(64, 4), 256>>>(x, W1);
    fvec1_kernel<<<64, 256>>>(a1_1, a2_1);
    max1_kernel<<<NH, 256>>>();
    bdf1_kernel<<<64, 256>>>();
    vbf_kernel<<<dim3(64, NH), 256>>>();
    attn1_wmma_kernel<<<dim3(64, NH), 128>>>();
    gemm2_kernel<<<256, 256>>>(W2, a1_2, a2_2);
    max2_kernel<<<1, 256>>>();
    bdf2_kernel<<<16, 256>>>();
    g2split_kernel<<<16, 256>>>();
    attn2_wmma_kernel<<<64, 128>>>(out);
}